// round 6
// baseline (speedup 1.0000x reference)
#include <cuda_runtime.h>
#include <math.h>

#define N_NODES 50000
#define N_EDGES 800000
#define NHEADS  8
#define MULT    16

// Scratch (device globals — no allocation allowed)
__device__ float g_e[(size_t)N_EDGES * NHEADS];   // exp scores (25.6 MB)
__device__ float g_s[(size_t)N_NODES * NHEADS];   // softmax denominators (1.6 MB)

// ---------------------------------------------------------------------------
// Pass 1 (proven R5): one (edge, head) per slot, TWO slots per thread at
// stride total/2 — coalesced float2 traffic + 2x MLP on random q gathers.
// ---------------------------------------------------------------------------
__global__ void __launch_bounds__(256) pass1_scores(
    const float* __restrict__ k0, const float* __restrict__ k1,
    const float* __restrict__ q0, const float* __restrict__ q1,
    const int* __restrict__ row_idx, const int* __restrict__ col_idx)
{
    const int HALF = N_EDGES * NHEADS / 2;   // 3.2M
    int t = blockIdx.x * blockDim.x + threadIdx.x;
    if (t >= HALF) return;

    int tA = t;
    int tB = t + HALF;
    int eA = tA >> 3, hA = tA & 7;
    int eB = tB >> 3, hB = tB & 7;

    int colA = __ldg(col_idx + eA);
    int colB = __ldg(col_idx + eB);
    int rwA  = __ldg(row_idx + eA);
    int rwB  = __ldg(row_idx + eB);

    float2 kaA = *(const float2*)(k0 + (size_t)eA   * 16 + 2 * hA);
    float2 kaB = *(const float2*)(k0 + (size_t)eB   * 16 + 2 * hB);
    float2 qaA = *(const float2*)(q0 + (size_t)colA * 16 + 2 * hA);
    float2 qaB = *(const float2*)(q0 + (size_t)colB * 16 + 2 * hB);

    const float2* k1A = (const float2*)(k1 + (size_t)eA   * 48 + 6 * hA);
    const float2* q1A = (const float2*)(q1 + (size_t)colA * 48 + 6 * hA);
    const float2* k1B = (const float2*)(k1 + (size_t)eB   * 48 + 6 * hB);
    const float2* q1B = (const float2*)(q1 + (size_t)colB * 48 + 6 * hB);

    float2 kA0 = k1A[0], kA1 = k1A[1], kA2 = k1A[2];
    float2 qA0 = q1A[0], qA1 = q1A[1], qA2 = q1A[2];
    float2 kB0 = k1B[0], kB1 = k1B[1], kB2 = k1B[2];
    float2 qB0 = q1B[0], qB1 = q1B[1], qB2 = q1B[2];

    float dA = kaA.x * qaA.x + kaA.y * qaA.y
             + kA0.x * qA0.x + kA0.y * qA0.y
             + kA1.x * qA1.x + kA1.y * qA1.y
             + kA2.x * qA2.x + kA2.y * qA2.y;
    float dB = kaB.x * qaB.x + kaB.y * qaB.y
             + kB0.x * qB0.x + kB0.y * qB0.y
             + kB1.x * qB1.x + kB1.y * qB1.y
             + kB2.x * qB2.x + kB2.y * qB2.y;

    float wA = expf(dA * 0.125f);   // 1/sqrt(64)
    float wB = expf(dB * 0.125f);

    g_e[tA] = wA;
    g_e[tB] = wB;

    atomicAdd(&g_s[rwA * NHEADS + hA], wA);
    atomicAdd(&g_s[rwB * NHEADS + hB], wB);
}

// ---------------------------------------------------------------------------
// Pass 2: ONE thread per edge. Cuts instruction count 48 -> ~28 per edge and
// L1 wavefronts ~35% vs the 4-thread version while keeping the same 16 v4
// REDs/edge (fire-and-forget, never stall). Loads grouped so v chunks are in
// flight while previous REDs issue; ~40 live regs.
// ---------------------------------------------------------------------------
__global__ void __launch_bounds__(256) pass2_scatter(
    const float* __restrict__ v0, const float* __restrict__ v1,
    const int* __restrict__ row_idx, const int* __restrict__ col_idx,
    float* __restrict__ out0, float* __restrict__ out1)
{
    int e = blockIdx.x * blockDim.x + threadIdx.x;
    if (e >= N_EDGES) return;

    int rw  = __ldg(row_idx + e);
    int col = __ldg(col_idx + e);

    // attn weights for all 8 heads: a[h] = g_e[e,h] / g_s[rw,h]
    const float4* ep = (const float4*)(g_e + (size_t)e  * NHEADS);
    const float4* sp = (const float4*)(g_s + (size_t)rw * NHEADS);
    float4 e0 = __ldg(ep),     e1 = __ldg(ep + 1);
    float4 s0 = __ldg(sp),     s1 = __ldg(sp + 1);

    float a[8];
    a[0] = e0.x * __fdividef(1.0f, s0.x);
    a[1] = e0.y * __fdividef(1.0f, s0.y);
    a[2] = e0.z * __fdividef(1.0f, s0.z);
    a[3] = e0.w * __fdividef(1.0f, s0.w);
    a[4] = e1.x * __fdividef(1.0f, s1.x);
    a[5] = e1.y * __fdividef(1.0f, s1.y);
    a[6] = e1.z * __fdividef(1.0f, s1.z);
    a[7] = e1.w * __fdividef(1.0f, s1.w);

    // ---- out0: 16 floats, head = g>>1 ----
    {
        const float4* vp = (const float4*)(v0 + (size_t)e * 16);
        float4 w0 = __ldg(vp), w1 = __ldg(vp + 1), w2 = __ldg(vp + 2), w3 = __ldg(vp + 3);
        float* p = out0 + (size_t)col * 16;
        asm volatile("red.global.add.v4.f32 [%0], {%1, %2, %3, %4};"
                     :: "l"(p), "f"(w0.x * a[0]), "f"(w0.y * a[0]),
                        "f"(w0.z * a[1]), "f"(w0.w * a[1]) : "memory");
        asm volatile("red.global.add.v4.f32 [%0], {%1, %2, %3, %4};"
                     :: "l"(p + 4), "f"(w1.x * a[2]), "f"(w1.y * a[2]),
                        "f"(w1.z * a[3]), "f"(w1.w * a[3]) : "memory");
        asm volatile("red.global.add.v4.f32 [%0], {%1, %2, %3, %4};"
                     :: "l"(p + 8), "f"(w2.x * a[4]), "f"(w2.y * a[4]),
                        "f"(w2.z * a[5]), "f"(w2.w * a[5]) : "memory");
        asm volatile("red.global.add.v4.f32 [%0], {%1, %2, %3, %4};"
                     :: "l"(p + 12), "f"(w3.x * a[6]), "f"(w3.y * a[6]),
                        "f"(w3.z * a[7]), "f"(w3.w * a[7]) : "memory");
    }

    // ---- out1: 48 floats, head = f/6 ; process in two 24-float halves ----
    const float4* vp = (const float4*)(v1 + (size_t)e * 48);
    float* p = out1 + (size_t)col * 48;

    {   // floats 0..23, heads 0..3
        float4 w0 = __ldg(vp),     w1 = __ldg(vp + 1), w2 = __ldg(vp + 2);
        float4 w3 = __ldg(vp + 3), w4 = __ldg(vp + 4), w5 = __ldg(vp + 5);
        asm volatile("red.global.add.v4.f32 [%0], {%1, %2, %3, %4};"
                     :: "l"(p), "f"(w0.x * a[0]), "f"(w0.y * a[0]),
                        "f"(w0.z * a[0]), "f"(w0.w * a[0]) : "memory");
        asm volatile("red.global.add.v4.f32 [%0], {%1, %2, %3, %4};"
                     :: "l"(p + 4), "f"(w1.x * a[0]), "f"(w1.y * a[0]),
                        "f"(w1.z * a[1]), "f"(w1.w * a[1]) : "memory");
        asm volatile("red.global.add.v4.f32 [%0], {%1, %2, %3, %4};"
                     :: "l"(p + 8), "f"(w2.x * a[1]), "f"(w2.y * a[1]),
                        "f"(w2.z * a[1]), "f"(w2.w * a[1]) : "memory");
        asm volatile("red.global.add.v4.f32 [%0], {%1, %2, %3, %4};"
                     :: "l"(p + 12), "f"(w3.x * a[2]), "f"(w3.y * a[2]),
                        "f"(w3.z * a[2]), "f"(w3.w * a[2]) : "memory");
        asm volatile("red.global.add.v4.f32 [%0], {%1, %2, %3, %4};"
                     :: "l"(p + 16), "f"(w4.x * a[2]), "f"(w4.y * a[2]),
                        "f"(w4.z * a[3]), "f"(w4.w * a[3]) : "memory");
        asm volatile("red.global.add.v4.f32 [%0], {%1, %2, %3, %4};"
                     :: "l"(p + 20), "f"(w5.x * a[3]), "f"(w5.y * a[3]),
                        "f"(w5.z * a[3]), "f"(w5.w * a[3]) : "memory");
    }
    {   // floats 24..47, heads 4..7
        float4 w0 = __ldg(vp + 6), w1 = __ldg(vp + 7),  w2 = __ldg(vp + 8);
        float4 w3 = __ldg(vp + 9), w4 = __ldg(vp + 10), w5 = __ldg(vp + 11);
        asm volatile("red.global.add.v4.f32 [%0], {%1, %2, %3, %4};"
                     :: "l"(p + 24), "f"(w0.x * a[4]), "f"(w0.y * a[4]),
                        "f"(w0.z * a[4]), "f"(w0.w * a[4]) : "memory");
        asm volatile("red.global.add.v4.f32 [%0], {%1, %2, %3, %4};"
                     :: "l"(p + 28), "f"(w1.x * a[4]), "f"(w1.y * a[4]),
                        "f"(w1.z * a[5]), "f"(w1.w * a[5]) : "memory");
        asm volatile("red.global.add.v4.f32 [%0], {%1, %2, %3, %4};"
                     :: "l"(p + 32), "f"(w2.x * a[5]), "f"(w2.y * a[5]),
                        "f"(w2.z * a[5]), "f"(w2.w * a[5]) : "memory");
        asm volatile("red.global.add.v4.f32 [%0], {%1, %2, %3, %4};"
                     :: "l"(p + 36), "f"(w3.x * a[6]), "f"(w3.y * a[6]),
                        "f"(w3.z * a[6]), "f"(w3.w * a[6]) : "memory");
        asm volatile("red.global.add.v4.f32 [%0], {%1, %2, %3, %4};"
                     :: "l"(p + 40), "f"(w4.x * a[6]), "f"(w4.y * a[6]),
                        "f"(w4.z * a[7]), "f"(w4.w * a[7]) : "memory");
        asm volatile("red.global.add.v4.f32 [%0], {%1, %2, %3, %4};"
                     :: "l"(p + 44), "f"(w5.x * a[7]), "f"(w5.y * a[7]),
                        "f"(w5.z * a[7]), "f"(w5.w * a[7]) : "memory");
    }
}

// ---------------------------------------------------------------------------
// Launch.  Inputs: v0, v1, k0, k1, q0, q1, edge_index
// Output: out0 (N*16) ++ out1 (N*48)
// ---------------------------------------------------------------------------
extern "C" void kernel_launch(void* const* d_in, const int* in_sizes, int n_in,
                              void* d_out, int out_size)
{
    const float* v0 = (const float*)d_in[0];
    const float* v1 = (const float*)d_in[1];
    const float* k0 = (const float*)d_in[2];
    const float* k1 = (const float*)d_in[3];
    const float* q0 = (const float*)d_in[4];
    const float* q1 = (const float*)d_in[5];
    const int*   ei = (const int*)  d_in[6];
    const int* row_idx = ei;             // edge_index[0]
    const int* col_idx = ei + N_EDGES;   // edge_index[1]

    float* out0 = (float*)d_out;
    float* out1 = out0 + (size_t)N_NODES * MULT;

    void* s_addr = nullptr;
    cudaGetSymbolAddress(&s_addr, g_s);

    cudaMemsetAsync(s_addr, 0, (size_t)N_NODES * NHEADS * sizeof(float));
    cudaMemsetAsync(d_out, 0, (size_t)out_size * sizeof(float));

    int half = N_EDGES * NHEADS / 2;
    pass1_scores<<<(half + 255) / 256, 256>>>(k0, k1, q0, q1, row_idx, col_idx);

    pass2_scatter<<<(N_EDGES + 255) / 256, 256>>>(v0, v1, row_idx, col_idx, out0, out1);
}

// round 7
// speedup vs baseline: 1.3807x; 1.3807x over previous
#include <cuda_runtime.h>
#include <math.h>

#define N_NODES 50000
#define N_EDGES 800000
#define NHEADS  8
#define MULT    16

// Scratch (device globals — no allocation allowed)
__device__ float g_e[(size_t)N_EDGES * NHEADS];   // exp scores (25.6 MB)
__device__ float g_s[(size_t)N_NODES * NHEADS];   // softmax denominators (1.6 MB)

// ---------------------------------------------------------------------------
// Pass 1 (proven R5): one (edge, head) per slot, TWO slots per thread at
// stride total/2 — coalesced float2 traffic + 2x MLP on random q gathers.
// ---------------------------------------------------------------------------
__global__ void __launch_bounds__(256) pass1_scores(
    const float* __restrict__ k0, const float* __restrict__ k1,
    const float* __restrict__ q0, const float* __restrict__ q1,
    const int* __restrict__ row_idx, const int* __restrict__ col_idx)
{
    const int HALF = N_EDGES * NHEADS / 2;   // 3.2M
    int t = blockIdx.x * blockDim.x + threadIdx.x;
    if (t >= HALF) return;

    int tA = t;
    int tB = t + HALF;
    int eA = tA >> 3, hA = tA & 7;
    int eB = tB >> 3, hB = tB & 7;

    int colA = __ldg(col_idx + eA);
    int colB = __ldg(col_idx + eB);
    int rwA  = __ldg(row_idx + eA);
    int rwB  = __ldg(row_idx + eB);

    float2 kaA = *(const float2*)(k0 + (size_t)eA   * 16 + 2 * hA);
    float2 kaB = *(const float2*)(k0 + (size_t)eB   * 16 + 2 * hB);
    float2 qaA = *(const float2*)(q0 + (size_t)colA * 16 + 2 * hA);
    float2 qaB = *(const float2*)(q0 + (size_t)colB * 16 + 2 * hB);

    const float2* k1A = (const float2*)(k1 + (size_t)eA   * 48 + 6 * hA);
    const float2* q1A = (const float2*)(q1 + (size_t)colA * 48 + 6 * hA);
    const float2* k1B = (const float2*)(k1 + (size_t)eB   * 48 + 6 * hB);
    const float2* q1B = (const float2*)(q1 + (size_t)colB * 48 + 6 * hB);

    float2 kA0 = k1A[0], kA1 = k1A[1], kA2 = k1A[2];
    float2 qA0 = q1A[0], qA1 = q1A[1], qA2 = q1A[2];
    float2 kB0 = k1B[0], kB1 = k1B[1], kB2 = k1B[2];
    float2 qB0 = q1B[0], qB1 = q1B[1], qB2 = q1B[2];

    float dA = kaA.x * qaA.x + kaA.y * qaA.y
             + kA0.x * qA0.x + kA0.y * qA0.y
             + kA1.x * qA1.x + kA1.y * qA1.y
             + kA2.x * qA2.x + kA2.y * qA2.y;
    float dB = kaB.x * qaB.x + kaB.y * qaB.y
             + kB0.x * qB0.x + kB0.y * qB0.y
             + kB1.x * qB1.x + kB1.y * qB1.y
             + kB2.x * qB2.x + kB2.y * qB2.y;

    float wA = expf(dA * 0.125f);   // 1/sqrt(64)
    float wB = expf(dB * 0.125f);

    g_e[tA] = wA;
    g_e[tB] = wB;

    atomicAdd(&g_s[rwA * NHEADS + hA], wA);
    atomicAdd(&g_s[rwB * NHEADS + hB], wB);
}

// ---------------------------------------------------------------------------
// Fetch attn coefficient for head h from within the 4-lane quad.
// Lane r of the quad holds a0 = a[2r], a1 = a[2r+1].
// ---------------------------------------------------------------------------
__device__ __forceinline__ float quad_a(float a0, float a1, int h)
{
    float s0 = __shfl_sync(0xFFFFFFFFu, a0, h >> 1, 4);
    float s1 = __shfl_sync(0xFFFFFFFFu, a1, h >> 1, 4);
    return (h & 1) ? s1 : s0;
}

// ---------------------------------------------------------------------------
// Pass 2: FOUR threads per edge (proven layout), but out1 chunk ownership is
// INTERLEAVED: thread q owns float4 chunks {q, 4+q, 8+q}. In each RED
// instruction the 4 lanes of an edge now cover one contiguous 64B piece ->
// L2 sector merging for both the v1 loads and the REDs (8 sector-RMWs/edge
// instead of 14). Head coefficients are exchanged within the quad via
// 4-wide shuffles. Denominator inversion fused (MUFU rcp).
// Grid is exact (3.2M threads / 256), no bounds check -> shuffles safe.
// ---------------------------------------------------------------------------
__global__ void __launch_bounds__(256) pass2_scatter(
    const float* __restrict__ v0, const float* __restrict__ v1,
    const int* __restrict__ row_idx, const int* __restrict__ col_idx,
    float* __restrict__ out0, float* __restrict__ out1)
{
    int t = blockIdx.x * blockDim.x + threadIdx.x;
    int e = t >> 2;
    int q = t & 3;

    int rw  = __ldg(row_idx + e);
    int col = __ldg(col_idx + e);

    // own heads 2q, 2q+1
    float2 ew = *(const float2*)(g_e + (size_t)e  * NHEADS + 2 * q);
    float2 sw = *(const float2*)(g_s + (size_t)rw * NHEADS + 2 * q);
    float a0 = ew.x * __fdividef(1.0f, sw.x);
    float a1 = ew.y * __fdividef(1.0f, sw.y);

    // ---- out0 chunk q: floats 4q..4q+3, heads {2q,2q,2q+1,2q+1} (own a's) --
    {
        float4 v = __ldg((const float4*)(v0 + (size_t)e * 16 + 4 * q));
        float* p = out0 + (size_t)col * 16 + 4 * q;
        asm volatile("red.global.add.v4.f32 [%0], {%1, %2, %3, %4};"
                     :: "l"(p), "f"(v.x * a0), "f"(v.y * a0),
                        "f"(v.z * a1), "f"(v.w * a1) : "memory");
    }

    // ---- out1 chunks c = 4j+q (j=0..2): floats 4c..4c+3, head = f/6 ----
    // Within chunk c: elements 0,1 use hlo=(2c)/3; elements 2,3 use
    // hlo+1 iff c%3==1, else hlo (pure chunk).
    const float4* vp = (const float4*)(v1 + (size_t)e * 48);
    float* p = out1 + (size_t)col * 48;

#pragma unroll
    for (int j = 0; j < 3; j++) {
        int c = 4 * j + q;
        float4 v = __ldg(vp + c);
        int hlo = (2 * c) / 3;
        int hhi = hlo + ((c % 3) == 1 ? 1 : 0);
        float mlo = quad_a(a0, a1, hlo);
        float mhi = quad_a(a0, a1, hhi);
        asm volatile("red.global.add.v4.f32 [%0], {%1, %2, %3, %4};"
                     :: "l"(p + 4 * c), "f"(v.x * mlo), "f"(v.y * mlo),
                        "f"(v.z * mhi), "f"(v.w * mhi) : "memory");
    }
}

// ---------------------------------------------------------------------------
// Launch.  Inputs: v0, v1, k0, k1, q0, q1, edge_index
// Output: out0 (N*16) ++ out1 (N*48)
// ---------------------------------------------------------------------------
extern "C" void kernel_launch(void* const* d_in, const int* in_sizes, int n_in,
                              void* d_out, int out_size)
{
    const float* v0 = (const float*)d_in[0];
    const float* v1 = (const float*)d_in[1];
    const float* k0 = (const float*)d_in[2];
    const float* k1 = (const float*)d_in[3];
    const float* q0 = (const float*)d_in[4];
    const float* q1 = (const float*)d_in[5];
    const int*   ei = (const int*)  d_in[6];
    const int* row_idx = ei;             // edge_index[0]
    const int* col_idx = ei + N_EDGES;   // edge_index[1]

    float* out0 = (float*)d_out;
    float* out1 = out0 + (size_t)N_NODES * MULT;

    void* s_addr = nullptr;
    cudaGetSymbolAddress(&s_addr, g_s);

    cudaMemsetAsync(s_addr, 0, (size_t)N_NODES * NHEADS * sizeof(float));
    cudaMemsetAsync(d_out, 0, (size_t)out_size * sizeof(float));

    int half = N_EDGES * NHEADS / 2;
    pass1_scores<<<(half + 255) / 256, 256>>>(k0, k1, q0, q1, row_idx, col_idx);

    int n2 = N_EDGES * 4;                 // 3.2M, divides 256 exactly
    pass2_scatter<<<n2 / 256, 256>>>(v0, v1, row_idx, col_idx, out0, out1);
}

// round 8
// speedup vs baseline: 1.3855x; 1.0034x over previous
#include <cuda_runtime.h>
#include <math.h>

#define N_NODES 50000
#define N_EDGES 800000
#define NHEADS  8
#define MULT    16

// Scratch (device globals — no allocation allowed)
__device__ float g_e[(size_t)N_EDGES * NHEADS];   // exp scores (25.6 MB)
__device__ float g_s[(size_t)N_NODES * NHEADS];   // softmax denominators (1.6 MB)

// ---------------------------------------------------------------------------
// Pass 1: one (edge, head) per slot, TWO slots per thread at stride total/2.
// New in R8:
//   - zeroes d_out (1 float/thread, coalesced) -> kills the 12.8MB memset
//   - denominator atomics paired via shuffle: even lane issues red.v2 for
//     heads {h, h+1} of its edge -> halves REDG lanes (6.4M -> 3.2M)
// Grid is exact (3.2M threads), no bounds check -> shuffles safe.
// ---------------------------------------------------------------------------
__global__ void __launch_bounds__(256) pass1_scores(
    const float* __restrict__ k0, const float* __restrict__ k1,
    const float* __restrict__ q0, const float* __restrict__ q1,
    const int* __restrict__ row_idx, const int* __restrict__ col_idx,
    float* __restrict__ out_zero)
{
    const int HALF = N_EDGES * NHEADS / 2;   // 3.2M
    int t = blockIdx.x * blockDim.x + threadIdx.x;

    out_zero[t] = 0.0f;   // d_out has exactly HALF floats (50000*64 = 3.2M)

    int tA = t;
    int tB = t + HALF;
    int eA = tA >> 3, hA = tA & 7;
    int eB = tB >> 3, hB = tB & 7;   // hB == hA

    int colA = __ldg(col_idx + eA);
    int colB = __ldg(col_idx + eB);
    int rwA  = __ldg(row_idx + eA);
    int rwB  = __ldg(row_idx + eB);

    float2 kaA = *(const float2*)(k0 + (size_t)eA   * 16 + 2 * hA);
    float2 kaB = *(const float2*)(k0 + (size_t)eB   * 16 + 2 * hB);
    float2 qaA = *(const float2*)(q0 + (size_t)colA * 16 + 2 * hA);
    float2 qaB = *(const float2*)(q0 + (size_t)colB * 16 + 2 * hB);

    const float2* k1A = (const float2*)(k1 + (size_t)eA   * 48 + 6 * hA);
    const float2* q1A = (const float2*)(q1 + (size_t)colA * 48 + 6 * hA);
    const float2* k1B = (const float2*)(k1 + (size_t)eB   * 48 + 6 * hB);
    const float2* q1B = (const float2*)(q1 + (size_t)colB * 48 + 6 * hB);

    float2 kA0 = k1A[0], kA1 = k1A[1], kA2 = k1A[2];
    float2 qA0 = q1A[0], qA1 = q1A[1], qA2 = q1A[2];
    float2 kB0 = k1B[0], kB1 = k1B[1], kB2 = k1B[2];
    float2 qB0 = q1B[0], qB1 = q1B[1], qB2 = q1B[2];

    float dA = kaA.x * qaA.x + kaA.y * qaA.y
             + kA0.x * qA0.x + kA0.y * qA0.y
             + kA1.x * qA1.x + kA1.y * qA1.y
             + kA2.x * qA2.x + kA2.y * qA2.y;
    float dB = kaB.x * qaB.x + kaB.y * qaB.y
             + kB0.x * qB0.x + kB0.y * qB0.y
             + kB1.x * qB1.x + kB1.y * qB1.y
             + kB2.x * qB2.x + kB2.y * qB2.y;

    float wA = expf(dA * 0.125f);   // 1/sqrt(64)
    float wB = expf(dB * 0.125f);

    g_e[tA] = wA;
    g_e[tB] = wB;

    // Pair heads {h, h+1} (same edge, same row) across lane pairs:
    // odd lane passes its w down; even lane issues one red.v2 per slot.
    float wA_hi = __shfl_down_sync(0xFFFFFFFFu, wA, 1);
    float wB_hi = __shfl_down_sync(0xFFFFFFFFu, wB, 1);
    if ((hA & 1) == 0) {
        float* pA = g_s + (size_t)rwA * NHEADS + hA;   // 8B aligned (h even)
        float* pB = g_s + (size_t)rwB * NHEADS + hB;
        asm volatile("red.global.add.v2.f32 [%0], {%1, %2};"
                     :: "l"(pA), "f"(wA), "f"(wA_hi) : "memory");
        asm volatile("red.global.add.v2.f32 [%0], {%1, %2};"
                     :: "l"(pB), "f"(wB), "f"(wB_hi) : "memory");
    }
}

// ---------------------------------------------------------------------------
// Quad-shuffle: lane r of the 4-lane quad holds a0=a[2r], a1=a[2r+1].
// ---------------------------------------------------------------------------
__device__ __forceinline__ float quad_a(float a0, float a1, int h)
{
    float s0 = __shfl_sync(0xFFFFFFFFu, a0, h >> 1, 4);
    float s1 = __shfl_sync(0xFFFFFFFFu, a1, h >> 1, 4);
    return (h & 1) ? s1 : s0;
}

// ---------------------------------------------------------------------------
// Pass 2 (R7 winner, unchanged): FOUR threads per edge, interleaved out1
// chunks {q, 4+q, 8+q} -> every RED instruction covers one contiguous 64B
// piece per edge (full L2 sector merging). Fused MUFU reciprocal.
// ---------------------------------------------------------------------------
__global__ void __launch_bounds__(256) pass2_scatter(
    const float* __restrict__ v0, const float* __restrict__ v1,
    const int* __restrict__ row_idx, const int* __restrict__ col_idx,
    float* __restrict__ out0, float* __restrict__ out1)
{
    int t = blockIdx.x * blockDim.x + threadIdx.x;
    int e = t >> 2;
    int q = t & 3;

    int rw  = __ldg(row_idx + e);
    int col = __ldg(col_idx + e);

    float2 ew = *(const float2*)(g_e + (size_t)e  * NHEADS + 2 * q);
    float2 sw = *(const float2*)(g_s + (size_t)rw * NHEADS + 2 * q);
    float a0 = ew.x * __fdividef(1.0f, sw.x);
    float a1 = ew.y * __fdividef(1.0f, sw.y);

    {
        float4 v = __ldg((const float4*)(v0 + (size_t)e * 16 + 4 * q));
        float* p = out0 + (size_t)col * 16 + 4 * q;
        asm volatile("red.global.add.v4.f32 [%0], {%1, %2, %3, %4};"
                     :: "l"(p), "f"(v.x * a0), "f"(v.y * a0),
                        "f"(v.z * a1), "f"(v.w * a1) : "memory");
    }

    const float4* vp = (const float4*)(v1 + (size_t)e * 48);
    float* p = out1 + (size_t)col * 48;

#pragma unroll
    for (int j = 0; j < 3; j++) {
        int c = 4 * j + q;
        float4 v = __ldg(vp + c);
        int hlo = (2 * c) / 3;
        int hhi = hlo + ((c % 3) == 1 ? 1 : 0);
        float mlo = quad_a(a0, a1, hlo);
        float mhi = quad_a(a0, a1, hhi);
        asm volatile("red.global.add.v4.f32 [%0], {%1, %2, %3, %4};"
                     :: "l"(p + 4 * c), "f"(v.x * mlo), "f"(v.y * mlo),
                        "f"(v.z * mhi), "f"(v.w * mhi) : "memory");
    }
}

// ---------------------------------------------------------------------------
// Launch.  Inputs: v0, v1, k0, k1, q0, q1, edge_index
// Output: out0 (N*16) ++ out1 (N*48)
// ---------------------------------------------------------------------------
extern "C" void kernel_launch(void* const* d_in, const int* in_sizes, int n_in,
                              void* d_out, int out_size)
{
    const float* v0 = (const float*)d_in[0];
    const float* v1 = (const float*)d_in[1];
    const float* k0 = (const float*)d_in[2];
    const float* k1 = (const float*)d_in[3];
    const float* q0 = (const float*)d_in[4];
    const float* q1 = (const float*)d_in[5];
    const int*   ei = (const int*)  d_in[6];
    const int* row_idx = ei;             // edge_index[0]
    const int* col_idx = ei + N_EDGES;   // edge_index[1]

    float* out0 = (float*)d_out;
    float* out1 = out0 + (size_t)N_NODES * MULT;

    void* s_addr = nullptr;
    cudaGetSymbolAddress(&s_addr, g_s);

    cudaMemsetAsync(s_addr, 0, (size_t)N_NODES * NHEADS * sizeof(float));
    // d_out zeroing folded into pass1 (out_size == N_EDGES*NHEADS/2 floats)

    int half = N_EDGES * NHEADS / 2;      // 3.2M, divides 256 exactly
    pass1_scores<<<half / 256, 256>>>(k0, k1, q0, q1, row_idx, col_idx,
                                      (float*)d_out);

    int n2 = N_EDGES * 4;                 // 3.2M, divides 256 exactly
    pass2_scatter<<<n2 / 256, 256>>>(v0, v1, row_idx, col_idx, out0, out1);
}